// round 4
// baseline (speedup 1.0000x reference)
#include <cuda_runtime.h>
#include <cstdint>

#define NN 20000
#define EE 640000
#define HH 128
#define TILE 128
#define EDGE_GRID (EE / TILE)   // 5000 exact
#define RPB 32                  // rows per block in node gemms (20000/32 = 625 exact)
#define SZ 132                  // padded smem stride (words)

// ---------------- scratch ----------------
__device__ float g_U[NN * HH];
__device__ float g_V[NN * HH];
__device__ float g_Zsum[NN * HH];
__device__ float g_M[NN * HH];
__device__ float g_T[NN * HH];
__device__ float g_h0[NN * HH];
__device__ float g_h1[NN * HH];
__device__ float g_x0[NN * 3];
__device__ float g_x1[NN * 3];
__device__ float g_deg[NN];
__device__ float g_D[HH * HH];    // eW2 @ cW1
__device__ float g_dvec[HH];      // eb2 @ cW1 + cb1
__device__ float g_Wuv[HH * 256]; // rearranged [k][0:128]=eW1a, [k][128:256]=eW1b
__device__ float g_buv[256];
__device__ int   g_hist[NN];
__device__ int   g_rowstart[NN + 1];
__device__ int   g_cursor[NN];
__device__ int   g_srow[EE];
__device__ int   g_scol[EE];

__device__ __forceinline__ uint32_t f2tf32(float f) {
    uint32_t r;
    asm("cvt.rna.tf32.f32 %0, %1;" : "=r"(r) : "f"(f));
    return r;
}

// ---------------- sort pipeline ----------------
__global__ void hist_kernel(const int* __restrict__ erow) {
    int e = blockIdx.x * 256 + threadIdx.x;
    if (e < EE) atomicAdd(&g_hist[erow[e]], 1);
}

__global__ void __launch_bounds__(1024) scan_kernel() {
    __shared__ int warp_sums[32];
    __shared__ int s_carry;
    const int tid = threadIdx.x;
    const int lane = tid & 31, wid = tid >> 5;
    if (tid == 0) s_carry = 0;
    __syncthreads();
    for (int base = 0; base < NN; base += 1024) {
        int i = base + tid;
        int v = (i < NN) ? g_hist[i] : 0;
        int x = v;
#pragma unroll
        for (int o = 1; o < 32; o <<= 1) {
            int y = __shfl_up_sync(0xffffffffu, x, o);
            if (lane >= o) x += y;
        }
        if (lane == 31) warp_sums[wid] = x;
        __syncthreads();
        if (wid == 0) {
            int w = warp_sums[lane];
#pragma unroll
            for (int o = 1; o < 32; o <<= 1) {
                int y = __shfl_up_sync(0xffffffffu, w, o);
                if (lane >= o) w += y;
            }
            warp_sums[lane] = w;
        }
        __syncthreads();
        int incl = x + (wid ? warp_sums[wid - 1] : 0) + s_carry;
        if (i < NN) g_rowstart[i] = incl - v;
        __syncthreads();
        if (tid == 1023) s_carry = incl;
        __syncthreads();
    }
    if (tid == 0) g_rowstart[NN] = s_carry;
}

__global__ void scatter_kernel(const int* __restrict__ erow, const int* __restrict__ ecol) {
    int e = blockIdx.x * 256 + threadIdx.x;
    if (e < EE) {
        int r = erow[e];
        int pos = g_rowstart[r] + atomicAdd(&g_cursor[r], 1);
        g_srow[pos] = r;
        g_scol[pos] = ecol[e];
    }
}

__global__ void degf_kernel() {
    int i = blockIdx.x * 256 + threadIdx.x;
    if (i < NN) g_deg[i] = (float)g_hist[i];
}

// ---------------- D = eW2 @ cW1, dvec = eb2 @ cW1 + cb1; Wuv rearrange ----------------
__global__ void precompD_kernel(const float* __restrict__ eW2, const float* __restrict__ cW1,
                                const float* __restrict__ eb2, const float* __restrict__ cb1) {
    int a = blockIdx.x, j = threadIdx.x;
    float s = 0.f;
#pragma unroll 8
    for (int m = 0; m < HH; m++)
        s = fmaf(__ldg(&eW2[a * HH + m]), __ldg(&cW1[m * HH + j]), s);
    g_D[a * HH + j] = s;
    if (a == 0) {
        float t = __ldg(&cb1[j]);
#pragma unroll 8
        for (int m = 0; m < HH; m++)
            t = fmaf(__ldg(&eb2[m]), __ldg(&cW1[m * HH + j]), t);
        g_dvec[j] = t;
    }
}

__global__ void wuv_kernel(const float* __restrict__ eW1, const float* __restrict__ eb1) {
    int k = blockIdx.x, j = threadIdx.x;
    g_Wuv[k * 256 + j] = eW1[k * HH + j];
    g_Wuv[k * 256 + 128 + j] = eW1[(HH + k) * HH + j];
    if (k == 0) {
        g_buv[j] = eb1[j];
        g_buv[128 + j] = 0.f;
    }
}

// ---------------- h0 = h @ emb_W + emb_b ----------------
__global__ void embed_kernel(const float* __restrict__ hin, const float* __restrict__ W,
                             const float* __restrict__ b) {
    int r = blockIdx.x, j = threadIdx.x;
    __shared__ float sh[16];
    if (j < 16) sh[j] = hin[r * 16 + j];
    __syncthreads();
    float acc = __ldg(&b[j]);
#pragma unroll
    for (int k = 0; k < 16; k++)
        acc = fmaf(sh[k], __ldg(&W[k * HH + j]), acc);
    g_h0[r * HH + j] = acc;
}

// ---------------- U|V fused node GEMM (256 output cols) ----------------
__global__ void __launch_bounds__(256)
gemm_uv(const float* __restrict__ A1, float* __restrict__ U, float* __restrict__ V) {
    __shared__ float sA[HH][36];
    const int r0 = blockIdx.x * RPB;
    const int j = threadIdx.x & 127;
    const int half = threadIdx.x >> 7;
#pragma unroll
    for (int ii = 0; ii < 16; ii++) {
        int i = half * 16 + ii;
        sA[j][i] = A1[(size_t)(r0 + i) * HH + j];
    }
    __syncthreads();

    const int jp = threadIdx.x;
    float acc[RPB];
    float b = g_buv[jp];
#pragma unroll
    for (int i = 0; i < RPB; i++) acc[i] = b;

#pragma unroll 4
    for (int k = 0; k < HH; k++) {
        float w = g_Wuv[k * 256 + jp];
#pragma unroll
        for (int i = 0; i < RPB; i += 4) {
            float4 a = *(const float4*)&sA[k][i];
            acc[i + 0] = fmaf(a.x, w, acc[i + 0]);
            acc[i + 1] = fmaf(a.y, w, acc[i + 1]);
            acc[i + 2] = fmaf(a.z, w, acc[i + 2]);
            acc[i + 3] = fmaf(a.w, w, acc[i + 3]);
        }
    }
    float* outp = (jp < 128) ? U : V;
    int jo = jp & 127;
#pragma unroll
    for (int i = 0; i < RPB; i++)
        outp[(size_t)(r0 + i) * HH + jo] = acc[i];
}

// ---------------- generic node GEMM ----------------
template <bool TWO, bool RELU, bool RESID, bool ROWSCALE>
__global__ void __launch_bounds__(128)
gemm128(const float* __restrict__ A1, const float* __restrict__ W1,
        const float* __restrict__ A2, const float* __restrict__ W2,
        const float* __restrict__ bias, const float* __restrict__ rowscale,
        const float* __restrict__ resid, float* __restrict__ C) {
    __shared__ float sA[HH][36];
    __shared__ float sB[TWO ? HH : 1][TWO ? 36 : 1];
    const int r0 = blockIdx.x * RPB;
    const int j = threadIdx.x;

#pragma unroll 8
    for (int i = 0; i < RPB; i++) sA[j][i] = A1[(size_t)(r0 + i) * HH + j];
    if (TWO) {
#pragma unroll 8
        for (int i = 0; i < RPB; i++) sB[j][i] = A2[(size_t)(r0 + i) * HH + j];
    }
    __syncthreads();

    float b = bias ? __ldg(&bias[j]) : 0.f;
    float acc[RPB];
#pragma unroll
    for (int i = 0; i < RPB; i++)
        acc[i] = ROWSCALE ? __ldg(&rowscale[r0 + i]) * b : b;

#pragma unroll 4
    for (int k = 0; k < HH; k++) {
        float w = __ldg(&W1[k * HH + j]);
#pragma unroll
        for (int i = 0; i < RPB; i += 4) {
            float4 a = *(const float4*)&sA[k][i];
            acc[i + 0] = fmaf(a.x, w, acc[i + 0]);
            acc[i + 1] = fmaf(a.y, w, acc[i + 1]);
            acc[i + 2] = fmaf(a.z, w, acc[i + 2]);
            acc[i + 3] = fmaf(a.w, w, acc[i + 3]);
        }
    }
    if (TWO) {
#pragma unroll 4
        for (int k = 0; k < HH; k++) {
            float w = __ldg(&W2[k * HH + j]);
#pragma unroll
            for (int i = 0; i < RPB; i += 4) {
                float4 a = *(const float4*)&sB[k][i];
                acc[i + 0] = fmaf(a.x, w, acc[i + 0]);
                acc[i + 1] = fmaf(a.y, w, acc[i + 1]);
                acc[i + 2] = fmaf(a.z, w, acc[i + 2]);
                acc[i + 3] = fmaf(a.w, w, acc[i + 3]);
            }
        }
    }
#pragma unroll
    for (int i = 0; i < RPB; i++) {
        float v = acc[i];
        if (RELU) v = fmaxf(v, 0.f);
        if (RESID) v += resid[(size_t)(r0 + i) * HH + j];
        C[(size_t)(r0 + i) * HH + j] = v;
    }
}

// ---------------- fused edge kernel (sorted rows; tf32 tensor-core phase B) ----------------
#define EDGE_SMEM_BYTES (2 * HH * SZ * 4 + 9 * HH * 4)

__global__ void __launch_bounds__(256, 1)
edge_kernel(const float* __restrict__ xin, const float* __restrict__ w3,
            const float* __restrict__ cW2, const float* __restrict__ cb2,
            float* __restrict__ xout) {
    extern __shared__ float sm[];
    float* Ds    = sm;                       // 128*132 (tf32 bits)
    float* zs    = Ds + HH * SZ;             // 128*132 (tf32 bits), [e][k]
    float* sdv   = zs + HH * SZ;
    float* sc2   = sdv + HH;
    float* sw3   = sc2 + HH;
    float* srd   = sw3 + HH;
    float* srelx = srd + HH;
    float* srely = srelx + HH;
    float* srelz = srely + HH;
    int*   ser   = (int*)(srelz + HH);
    int*   sec   = ser + HH;

    const int tid  = threadIdx.x;
    const int lane = tid & 31;
    const int warp = tid >> 5;

    // load D into smem as tf32
    {
        const float4* D4 = (const float4*)g_D;
#pragma unroll
        for (int it = 0; it < 16; it++) {
            int l = tid + 256 * it;
            int row = l >> 5;
            int c4  = l & 31;
            float4 d = D4[l];
            uint4 t;
            t.x = f2tf32(d.x); t.y = f2tf32(d.y);
            t.z = f2tf32(d.z); t.w = f2tf32(d.w);
            *(uint4*)(Ds + row * SZ + c4 * 4) = t;
        }
    }
    if (tid < HH) {
        sdv[tid] = g_dvec[tid];
        sc2[tid] = __ldg(&cW2[tid]);
        sw3[tid] = __ldg(&w3[tid]);
    }
    const float cb2v = __ldg(cb2);

    const int e0 = blockIdx.x * TILE;

    // ---- phase A0: per-edge geometry (sorted edges) ----
    if (tid < TILE) {
        int e = e0 + tid;
        int r = g_srow[e];
        int c = g_scol[e];
        float dx = __ldg(&xin[3 * r + 0]) - __ldg(&xin[3 * c + 0]);
        float dy = __ldg(&xin[3 * r + 1]) - __ldg(&xin[3 * c + 1]);
        float dz = __ldg(&xin[3 * r + 2]) - __ldg(&xin[3 * c + 2]);
        ser[tid] = r; sec[tid] = c;
        srelx[tid] = dx; srely[tid] = dy; srelz[tid] = dz;
        srd[tid] = dx * dx + dy * dy + dz * dz;
    }
    __syncthreads();

    // ---- phase A1: z1 + segmented Zsum reduction (rows sorted within warp range) ----
    {
        float4 w = ((const float4*)sw3)[lane];
        float4 acc = make_float4(0.f, 0.f, 0.f, 0.f);
        int cur = ser[warp * 16];
#pragma unroll 4
        for (int ee = 0; ee < 16; ee++) {
            int eL = warp * 16 + ee;
            int r = ser[eL], c = sec[eL];
            float rd = srd[eL];
            const float4* Up = (const float4*)(g_U + (size_t)r * HH);
            const float4* Vp = (const float4*)(g_V + (size_t)c * HH);
            float4 u = __ldg(Up + lane);
            float4 v = __ldg(Vp + lane);
            float4 z;
            z.x = fmaxf(u.x + v.x + rd * w.x, 0.f);
            z.y = fmaxf(u.y + v.y + rd * w.y, 0.f);
            z.z = fmaxf(u.z + v.z + rd * w.z, 0.f);
            z.w = fmaxf(u.w + v.w + rd * w.w, 0.f);
            if (r != cur) {
                float* zp = g_Zsum + (size_t)cur * HH + lane * 4;
                asm volatile("red.global.add.v4.f32 [%0], {%1, %2, %3, %4};"
                             :: "l"(zp), "f"(acc.x), "f"(acc.y), "f"(acc.z), "f"(acc.w)
                             : "memory");
                acc = make_float4(0.f, 0.f, 0.f, 0.f);
                cur = r;
            }
            acc.x += z.x; acc.y += z.y; acc.z += z.z; acc.w += z.w;
            uint4 t;
            t.x = f2tf32(z.x); t.y = f2tf32(z.y);
            t.z = f2tf32(z.z); t.w = f2tf32(z.w);
            *(uint4*)(zs + eL * SZ + lane * 4) = t;
        }
        float* zp = g_Zsum + (size_t)cur * HH + lane * 4;
        asm volatile("red.global.add.v4.f32 [%0], {%1, %2, %3, %4};"
                     :: "l"(zp), "f"(acc.x), "f"(acc.y), "f"(acc.z), "f"(acc.w)
                     : "memory");
    }
    __syncthreads();

    // ---- phase B: a_in = z1 @ D via mma.sync m16n8k8 tf32 ----
    const int qr = lane >> 2;
    const int lr = lane & 3;
    const int m0 = warp * 16;

    uint32_t a[16][4];
    {
        const uint32_t* zb0 = (const uint32_t*)zs + (m0 + qr) * SZ;
        const uint32_t* zb1 = zb0 + 8 * SZ;
#pragma unroll
        for (int kt = 0; kt < 16; kt++) {
            int k0 = kt * 8 + lr;
            a[kt][0] = zb0[k0];
            a[kt][1] = zb1[k0];
            a[kt][2] = zb0[k0 + 4];
            a[kt][3] = zb1[k0 + 4];
        }
    }

    float c0[16], c1[16], c2[16], c3[16];
#pragma unroll
    for (int nt = 0; nt < 16; nt++) { c0[nt] = 0.f; c1[nt] = 0.f; c2[nt] = 0.f; c3[nt] = 0.f; }

    const uint32_t* Du = (const uint32_t*)Ds;
#pragma unroll
    for (int nt = 0; nt < 16; nt++) {
        const uint32_t* db = Du + lr * SZ + nt * 8 + qr;
#pragma unroll
        for (int kt = 0; kt < 16; kt++) {
            uint32_t b0 = db[kt * 8 * SZ];
            uint32_t b1 = db[kt * 8 * SZ + 4 * SZ];
            asm volatile(
                "mma.sync.aligned.m16n8k8.row.col.f32.tf32.tf32.f32 "
                "{%0,%1,%2,%3}, {%4,%5,%6,%7}, {%8,%9}, {%0,%1,%2,%3};"
                : "+f"(c0[nt]), "+f"(c1[nt]), "+f"(c2[nt]), "+f"(c3[nt])
                : "r"(a[kt][0]), "r"(a[kt][1]), "r"(a[kt][2]), "r"(a[kt][3]),
                  "r"(b0), "r"(b1));
        }
    }

    // ---- phase C: alpha + x scatter ----
    float s0 = 0.f, s1 = 0.f;
#pragma unroll
    for (int nt = 0; nt < 16; nt++) {
        int j0 = nt * 8 + 2 * lr;
        float dva = sdv[j0], dvb = sdv[j0 + 1];
        float wa = sc2[j0], wb = sc2[j0 + 1];
        s0 = fmaf(fmaxf(c0[nt] + dva, 0.f), wa, s0);
        s0 = fmaf(fmaxf(c1[nt] + dvb, 0.f), wb, s0);
        s1 = fmaf(fmaxf(c2[nt] + dva, 0.f), wa, s1);
        s1 = fmaf(fmaxf(c3[nt] + dvb, 0.f), wb, s1);
    }
    s0 += __shfl_xor_sync(0xffffffffu, s0, 1);
    s0 += __shfl_xor_sync(0xffffffffu, s0, 2);
    s1 += __shfl_xor_sync(0xffffffffu, s1, 1);
    s1 += __shfl_xor_sync(0xffffffffu, s1, 2);

    if (lr == 0) {
        int eA = m0 + qr;
        int eB = m0 + qr + 8;
        float aA = s0 + cb2v;
        float aB = s1 + cb2v;
        int rA = ser[eA], rB = ser[eB];
        atomicAdd(&xout[3 * rA + 0], aA * srelx[eA]);
        atomicAdd(&xout[3 * rA + 1], aA * srely[eA]);
        atomicAdd(&xout[3 * rA + 2], aA * srelz[eA]);
        atomicAdd(&xout[3 * rB + 0], aB * srelx[eB]);
        atomicAdd(&xout[3 * rB + 1], aB * srely[eB]);
        atomicAdd(&xout[3 * rB + 2], aB * srelz[eB]);
    }
}

// ---------------- host launch ----------------
extern "C" void kernel_launch(void* const* d_in, const int* in_sizes, int n_in,
                              void* d_out, int out_size) {
    const float* h    = (const float*)d_in[0];
    const float* x    = (const float*)d_in[1];
    const int*   ei   = (const int*)d_in[2];
    const float* embW = (const float*)d_in[3];
    const float* embb = (const float*)d_in[4];
    const float* eW1  = (const float*)d_in[5];
    const float* eb1  = (const float*)d_in[6];
    const float* eW2  = (const float*)d_in[7];
    const float* eb2  = (const float*)d_in[8];
    const float* nW1  = (const float*)d_in[9];
    const float* nb1  = (const float*)d_in[10];
    const float* nW2  = (const float*)d_in[11];
    const float* nb2  = (const float*)d_in[12];
    const float* cW1  = (const float*)d_in[13];
    const float* cb1  = (const float*)d_in[14];
    const float* cW2  = (const float*)d_in[15];
    const float* cb2  = (const float*)d_in[16];
    const int* erow = ei;
    const int* ecol = ei + EE;
    float* out = (float*)d_out;

    void* p;
    float *pU, *pV, *pZ, *pM, *pT, *pH0, *pH1, *pX0, *pX1, *pDeg;
    int *pHist, *pCursor;
    cudaGetSymbolAddress(&p, g_U);      pU  = (float*)p;
    cudaGetSymbolAddress(&p, g_V);      pV  = (float*)p;
    cudaGetSymbolAddress(&p, g_Zsum);   pZ  = (float*)p;
    cudaGetSymbolAddress(&p, g_M);      pM  = (float*)p;
    cudaGetSymbolAddress(&p, g_T);      pT  = (float*)p;
    cudaGetSymbolAddress(&p, g_h0);     pH0 = (float*)p;
    cudaGetSymbolAddress(&p, g_h1);     pH1 = (float*)p;
    cudaGetSymbolAddress(&p, g_x0);     pX0 = (float*)p;
    cudaGetSymbolAddress(&p, g_x1);     pX1 = (float*)p;
    cudaGetSymbolAddress(&p, g_deg);    pDeg = (float*)p;
    cudaGetSymbolAddress(&p, g_hist);   pHist = (int*)p;
    cudaGetSymbolAddress(&p, g_cursor); pCursor = (int*)p;

    cudaFuncSetAttribute(edge_kernel, cudaFuncAttributeMaxDynamicSharedMemorySize,
                         EDGE_SMEM_BYTES);

    // ---- per-call precompute: sort edges by row + weights ----
    cudaMemsetAsync(pHist, 0, NN * sizeof(int));
    hist_kernel<<<EE / 256, 256>>>(erow);
    scan_kernel<<<1, 1024>>>();
    cudaMemsetAsync(pCursor, 0, NN * sizeof(int));
    scatter_kernel<<<EE / 256, 256>>>(erow, ecol);
    degf_kernel<<<(NN + 255) / 256, 256>>>();
    precompD_kernel<<<HH, HH>>>(eW2, cW1, eb2, cb1);
    wuv_kernel<<<HH, HH>>>(eW1, eb1);
    embed_kernel<<<NN, HH>>>(h, embW, embb);
    cudaMemcpyAsync(pX0, x, NN * 3 * sizeof(float), cudaMemcpyDeviceToDevice);

    const int GB = NN / RPB;  // 625

    for (int l = 0; l < 2; l++) {
        const float* hi = (l == 0) ? pH0 : pH1;
        float*       ho = (l == 0) ? pH1 : out;
        const float* xi = (l == 0) ? pX0 : pX1;
        float*       xo = (l == 0) ? pX1 : out + (size_t)NN * HH;

        cudaMemsetAsync(pZ, 0, (size_t)NN * HH * sizeof(float));
        cudaMemcpyAsync(xo, xi, NN * 3 * sizeof(float), cudaMemcpyDeviceToDevice);

        // U|V fused: U = hi @ eW1a + eb1 ; V = hi @ eW1b
        gemm_uv<<<GB, 256>>>(hi, pU, pV);
        // fused edge pass (sorted edges)
        edge_kernel<<<EDGE_GRID, 256, EDGE_SMEM_BYTES>>>(xi, eW1 + 256 * HH, cW2, cb2, xo);
        // M = Zsum @ eW2 + deg * eb2
        gemm128<false, false, false, true><<<GB, HH>>>(pZ, eW2, nullptr, nullptr,
                                                       eb2, pDeg, nullptr, pM);
        // T = relu(hi @ nW1a + M @ nW1b + nb1)
        gemm128<true, true, false, false><<<GB, HH>>>(hi, nW1, pM, nW1 + HH * HH,
                                                      nb1, nullptr, nullptr, pT);
        // ho = hi + T @ nW2 + nb2
        gemm128<false, false, true, false><<<GB, HH>>>(pT, nW2, nullptr, nullptr,
                                                       nb2, nullptr, hi, ho);
    }
    (void)in_sizes; (void)n_in; (void)out_size;
}

// round 5
// speedup vs baseline: 1.2615x; 1.2615x over previous
#include <cuda_runtime.h>
#include <cstdint>

#define NN 20000
#define EE 640000
#define HH 128
#define TILE_E 256
#define EDGE_GRID (EE / TILE_E) // 2500 exact
#define RPB 32                  // rows per block in node gemms
#define SZ 132                  // padded smem stride (words)

// ---------------- scratch ----------------
__device__ float g_U[NN * HH];
__device__ float g_V[NN * HH];
__device__ float g_Zsum[NN * HH];
__device__ float g_M[NN * HH];
__device__ float g_T[NN * HH];
__device__ float g_h0[NN * HH];
__device__ float g_h1[NN * HH];
__device__ float g_x0[NN * 3];
__device__ float g_x1[NN * 3];
__device__ float g_deg[NN];
__device__ float g_D[HH * HH];    // eW2 @ cW1
__device__ float g_dvec[HH];      // eb2 @ cW1 + cb1
__device__ float g_Wuv[HH * 256]; // [k][0:128]=eW1a, [k][128:256]=eW1b
__device__ float g_buv[256];

__device__ __forceinline__ uint32_t f2tf32(float f) {
    uint32_t r;
    asm("cvt.rna.tf32.f32 %0, %1;" : "=r"(r) : "f"(f));
    return r;
}

// ---------------- degree ----------------
__global__ void deg_kernel(const int* __restrict__ erow) {
    int e = blockIdx.x * 256 + threadIdx.x;
    if (e < EE) atomicAdd(&g_deg[erow[e]], 1.0f);
}

// ---------------- D = eW2 @ cW1, dvec = eb2 @ cW1 + cb1 ----------------
__global__ void precompD_kernel(const float* __restrict__ eW2, const float* __restrict__ cW1,
                                const float* __restrict__ eb2, const float* __restrict__ cb1) {
    int a = blockIdx.x, j = threadIdx.x;
    float s = 0.f;
#pragma unroll 8
    for (int m = 0; m < HH; m++)
        s = fmaf(__ldg(&eW2[a * HH + m]), __ldg(&cW1[m * HH + j]), s);
    g_D[a * HH + j] = s;
    if (a == 0) {
        float t = __ldg(&cb1[j]);
#pragma unroll 8
        for (int m = 0; m < HH; m++)
            t = fmaf(__ldg(&eb2[m]), __ldg(&cW1[m * HH + j]), t);
        g_dvec[j] = t;
    }
}

__global__ void wuv_kernel(const float* __restrict__ eW1, const float* __restrict__ eb1) {
    int k = blockIdx.x, j = threadIdx.x;
    g_Wuv[k * 256 + j] = eW1[k * HH + j];
    g_Wuv[k * 256 + 128 + j] = eW1[(HH + k) * HH + j];
    if (k == 0) {
        g_buv[j] = eb1[j];
        g_buv[128 + j] = 0.f;
    }
}

// ---------------- h0 = h @ emb_W + emb_b ----------------
__global__ void embed_kernel(const float* __restrict__ hin, const float* __restrict__ W,
                             const float* __restrict__ b) {
    int r = blockIdx.x, j = threadIdx.x;
    __shared__ float sh[16];
    if (j < 16) sh[j] = hin[r * 16 + j];
    __syncthreads();
    float acc = __ldg(&b[j]);
#pragma unroll
    for (int k = 0; k < 16; k++)
        acc = fmaf(sh[k], __ldg(&W[k * HH + j]), acc);
    g_h0[r * HH + j] = acc;
}

// ---------------- U|V fused node GEMM (256 output cols) ----------------
__global__ void __launch_bounds__(256)
gemm_uv(const float* __restrict__ A1, float* __restrict__ U, float* __restrict__ V) {
    __shared__ float sA[HH][36];
    const int r0 = blockIdx.x * RPB;
    const int j = threadIdx.x & 127;
    const int half = threadIdx.x >> 7;
#pragma unroll
    for (int ii = 0; ii < 16; ii++) {
        int i = half * 16 + ii;
        sA[j][i] = A1[(size_t)(r0 + i) * HH + j];
    }
    __syncthreads();

    const int jp = threadIdx.x;
    float acc[RPB];
    float b = g_buv[jp];
#pragma unroll
    for (int i = 0; i < RPB; i++) acc[i] = b;

#pragma unroll 4
    for (int k = 0; k < HH; k++) {
        float w = g_Wuv[k * 256 + jp];
#pragma unroll
        for (int i = 0; i < RPB; i += 4) {
            float4 a = *(const float4*)&sA[k][i];
            acc[i + 0] = fmaf(a.x, w, acc[i + 0]);
            acc[i + 1] = fmaf(a.y, w, acc[i + 1]);
            acc[i + 2] = fmaf(a.z, w, acc[i + 2]);
            acc[i + 3] = fmaf(a.w, w, acc[i + 3]);
        }
    }
    float* outp = (jp < 128) ? U : V;
    int jo = jp & 127;
#pragma unroll
    for (int i = 0; i < RPB; i++)
        outp[(size_t)(r0 + i) * HH + jo] = acc[i];
}

// ---------------- generic node GEMM ----------------
template <bool TWO, bool RELU, bool RESID, bool ROWSCALE>
__global__ void __launch_bounds__(128)
gemm128(const float* __restrict__ A1, const float* __restrict__ W1,
        const float* __restrict__ A2, const float* __restrict__ W2,
        const float* __restrict__ bias, const float* __restrict__ rowscale,
        const float* __restrict__ resid, float* __restrict__ C) {
    __shared__ float sA[HH][36];
    __shared__ float sB[TWO ? HH : 1][TWO ? 36 : 1];
    const int r0 = blockIdx.x * RPB;
    const int j = threadIdx.x;

#pragma unroll 8
    for (int i = 0; i < RPB; i++) sA[j][i] = A1[(size_t)(r0 + i) * HH + j];
    if (TWO) {
#pragma unroll 8
        for (int i = 0; i < RPB; i++) sB[j][i] = A2[(size_t)(r0 + i) * HH + j];
    }
    __syncthreads();

    float b = bias ? __ldg(&bias[j]) : 0.f;
    float acc[RPB];
#pragma unroll
    for (int i = 0; i < RPB; i++)
        acc[i] = ROWSCALE ? __ldg(&rowscale[r0 + i]) * b : b;

#pragma unroll 4
    for (int k = 0; k < HH; k++) {
        float w = __ldg(&W1[k * HH + j]);
#pragma unroll
        for (int i = 0; i < RPB; i += 4) {
            float4 a = *(const float4*)&sA[k][i];
            acc[i + 0] = fmaf(a.x, w, acc[i + 0]);
            acc[i + 1] = fmaf(a.y, w, acc[i + 1]);
            acc[i + 2] = fmaf(a.z, w, acc[i + 2]);
            acc[i + 3] = fmaf(a.w, w, acc[i + 3]);
        }
    }
    if (TWO) {
#pragma unroll 4
        for (int k = 0; k < HH; k++) {
            float w = __ldg(&W2[k * HH + j]);
#pragma unroll
            for (int i = 0; i < RPB; i += 4) {
                float4 a = *(const float4*)&sB[k][i];
                acc[i + 0] = fmaf(a.x, w, acc[i + 0]);
                acc[i + 1] = fmaf(a.y, w, acc[i + 1]);
                acc[i + 2] = fmaf(a.z, w, acc[i + 2]);
                acc[i + 3] = fmaf(a.w, w, acc[i + 3]);
            }
        }
    }
#pragma unroll
    for (int i = 0; i < RPB; i++) {
        float v = acc[i];
        if (RELU) v = fmaxf(v, 0.f);
        if (RESID) v += resid[(size_t)(r0 + i) * HH + j];
        C[(size_t)(r0 + i) * HH + j] = v;
    }
}

// ---------------- fused edge kernel: 256-edge tiles, tf32 mma with B-frag reuse ----------------
// smem: Ds 128x132 (tf32), zs 256x132 (tf32), per-edge arrays
#define EDGE_SMEM_BYTES ((HH * SZ + TILE_E * SZ + 3 * HH + 6 * TILE_E) * 4)

__global__ void __launch_bounds__(256, 1)
edge_kernel(const int* __restrict__ erow, const int* __restrict__ ecol,
            const float* __restrict__ xin, const float* __restrict__ w3,
            const float* __restrict__ cW2, const float* __restrict__ cb2,
            float* __restrict__ xout) {
    extern __shared__ float sm[];
    float* Ds    = sm;                       // 128*132 tf32
    float* zs    = Ds + HH * SZ;             // 256*132 tf32, [e][k]
    float* sdv   = zs + TILE_E * SZ;         // 128
    float* sc2   = sdv + HH;                 // 128
    float* sw3   = sc2 + HH;                 // 128
    float* srd   = sw3 + HH;                 // 256
    float* srelx = srd + TILE_E;             // 256
    float* srely = srelx + TILE_E;           // 256
    float* srelz = srely + TILE_E;           // 256
    int*   ser   = (int*)(srelz + TILE_E);   // 256
    int*   sec   = ser + TILE_E;             // 256

    const int tid  = threadIdx.x;
    const int lane = tid & 31;
    const int warp = tid >> 5;

    // ---- load D into smem as tf32 ----
    {
        const float4* D4 = (const float4*)g_D;
#pragma unroll
        for (int it = 0; it < 16; it++) {
            int l = tid + 256 * it;
            int row = l >> 5;
            int c4  = l & 31;
            float4 d = D4[l];
            uint4 t;
            t.x = f2tf32(d.x); t.y = f2tf32(d.y);
            t.z = f2tf32(d.z); t.w = f2tf32(d.w);
            *(uint4*)(Ds + row * SZ + c4 * 4) = t;
        }
    }
    if (tid < HH) {
        sdv[tid] = g_dvec[tid];
        sc2[tid] = __ldg(&cW2[tid]);
        sw3[tid] = __ldg(&w3[tid]);
    }
    const float cb2v = __ldg(cb2);

    const int e0 = blockIdx.x * TILE_E;

    // ---- phase A0: per-edge geometry (256 edges, 1 per thread) ----
    {
        int e = e0 + tid;
        int r = erow[e];
        int c = ecol[e];
        float dx = __ldg(&xin[3 * r + 0]) - __ldg(&xin[3 * c + 0]);
        float dy = __ldg(&xin[3 * r + 1]) - __ldg(&xin[3 * c + 1]);
        float dz = __ldg(&xin[3 * r + 2]) - __ldg(&xin[3 * c + 2]);
        ser[tid] = r; sec[tid] = c;
        srelx[tid] = dx; srely[tid] = dy; srelz[tid] = dz;
        srd[tid] = dx * dx + dy * dy + dz * dz;
    }
    __syncthreads();

    // ---- phase A1: z1 = relu(U[row]+V[col]+rd*w3); red into Zsum; tf32 into zs ----
    {
        float4 w = ((const float4*)sw3)[lane];
#pragma unroll 4
        for (int ee = 0; ee < 32; ee++) {
            int eL = warp * 32 + ee;
            int r = ser[eL], c = sec[eL];
            float rd = srd[eL];
            const float4* Up = (const float4*)(g_U + (size_t)r * HH);
            const float4* Vp = (const float4*)(g_V + (size_t)c * HH);
            float4 u = __ldg(Up + lane);
            float4 v = __ldg(Vp + lane);
            float4 z;
            z.x = fmaxf(u.x + v.x + rd * w.x, 0.f);
            z.y = fmaxf(u.y + v.y + rd * w.y, 0.f);
            z.z = fmaxf(u.z + v.z + rd * w.z, 0.f);
            z.w = fmaxf(u.w + v.w + rd * w.w, 0.f);
            float* zp = g_Zsum + (size_t)r * HH + lane * 4;
            asm volatile("red.global.add.v4.f32 [%0], {%1, %2, %3, %4};"
                         :: "l"(zp), "f"(z.x), "f"(z.y), "f"(z.z), "f"(z.w)
                         : "memory");
            uint4 t;
            t.x = f2tf32(z.x); t.y = f2tf32(z.y);
            t.z = f2tf32(z.z); t.w = f2tf32(z.w);
            *(uint4*)(zs + eL * SZ + lane * 4) = t;
        }
    }
    __syncthreads();

    // ---- phase B: a_in = z1 @ D ; each warp: 32 edges (2 m-tiles) x 128 N ----
    const int qr = lane >> 2;    // 0..7
    const int lr = lane & 3;     // 0..3
    const int m0 = warp * 32;

    float cA0[16], cA1[16], cA2[16], cA3[16];   // m-tile 0: edges m0+qr, m0+qr+8
    float cB0[16], cB1[16], cB2[16], cB3[16];   // m-tile 1: edges m0+16+qr, m0+24+qr
#pragma unroll
    for (int nt = 0; nt < 16; nt++) {
        cA0[nt] = 0.f; cA1[nt] = 0.f; cA2[nt] = 0.f; cA3[nt] = 0.f;
        cB0[nt] = 0.f; cB1[nt] = 0.f; cB2[nt] = 0.f; cB3[nt] = 0.f;
    }

    const uint32_t* Du = (const uint32_t*)Ds;
    const uint32_t* z0 = (const uint32_t*)zs + (m0 + qr) * SZ;
    const uint32_t* z1 = z0 + 16 * SZ;

#pragma unroll
    for (int kt = 0; kt < 16; kt++) {
        const int k0 = kt * 8 + lr;
        uint32_t a00 = z0[k0];
        uint32_t a01 = z0[8 * SZ + k0];
        uint32_t a02 = z0[k0 + 4];
        uint32_t a03 = z0[8 * SZ + k0 + 4];
        uint32_t a10 = z1[k0];
        uint32_t a11 = z1[8 * SZ + k0];
        uint32_t a12 = z1[k0 + 4];
        uint32_t a13 = z1[8 * SZ + k0 + 4];
        const uint32_t* db = Du + (lr + kt * 8) * SZ + qr;
#pragma unroll
        for (int nt = 0; nt < 16; nt++) {
            uint32_t b0 = db[nt * 8];
            uint32_t b1 = db[4 * SZ + nt * 8];
            asm volatile(
                "mma.sync.aligned.m16n8k8.row.col.f32.tf32.tf32.f32 "
                "{%0,%1,%2,%3}, {%4,%5,%6,%7}, {%8,%9}, {%0,%1,%2,%3};"
                : "+f"(cA0[nt]), "+f"(cA1[nt]), "+f"(cA2[nt]), "+f"(cA3[nt])
                : "r"(a00), "r"(a01), "r"(a02), "r"(a03), "r"(b0), "r"(b1));
            asm volatile(
                "mma.sync.aligned.m16n8k8.row.col.f32.tf32.tf32.f32 "
                "{%0,%1,%2,%3}, {%4,%5,%6,%7}, {%8,%9}, {%0,%1,%2,%3};"
                : "+f"(cB0[nt]), "+f"(cB1[nt]), "+f"(cB2[nt]), "+f"(cB3[nt])
                : "r"(a10), "r"(a11), "r"(a12), "r"(a13), "r"(b0), "r"(b1));
        }
    }

    // ---- phase C: alpha = relu(a_in + dvec) . cW2 + cb2 ; scatter alpha*rel ----
    float s0 = 0.f, s1 = 0.f, s2 = 0.f, s3 = 0.f;
#pragma unroll
    for (int nt = 0; nt < 16; nt++) {
        int j0 = nt * 8 + 2 * lr;
        float dva = sdv[j0], dvb = sdv[j0 + 1];
        float wa = sc2[j0], wb = sc2[j0 + 1];
        s0 = fmaf(fmaxf(cA0[nt] + dva, 0.f), wa, s0);
        s0 = fmaf(fmaxf(cA1[nt] + dvb, 0.f), wb, s0);
        s1 = fmaf(fmaxf(cA2[nt] + dva, 0.f), wa, s1);
        s1 = fmaf(fmaxf(cA3[nt] + dvb, 0.f), wb, s1);
        s2 = fmaf(fmaxf(cB0[nt] + dva, 0.f), wa, s2);
        s2 = fmaf(fmaxf(cB1[nt] + dvb, 0.f), wb, s2);
        s3 = fmaf(fmaxf(cB2[nt] + dva, 0.f), wa, s3);
        s3 = fmaf(fmaxf(cB3[nt] + dvb, 0.f), wb, s3);
    }
#pragma unroll
    for (int off = 1; off <= 2; off <<= 1) {
        s0 += __shfl_xor_sync(0xffffffffu, s0, off);
        s1 += __shfl_xor_sync(0xffffffffu, s1, off);
        s2 += __shfl_xor_sync(0xffffffffu, s2, off);
        s3 += __shfl_xor_sync(0xffffffffu, s3, off);
    }

    if (lr == 0) {
        int eIdx[4] = {m0 + qr, m0 + qr + 8, m0 + 16 + qr, m0 + 24 + qr};
        float sv[4] = {s0, s1, s2, s3};
#pragma unroll
        for (int i = 0; i < 4; i++) {
            int eL = eIdx[i];
            float a = sv[i] + cb2v;
            int r = ser[eL];
            atomicAdd(&xout[3 * r + 0], a * srelx[eL]);
            atomicAdd(&xout[3 * r + 1], a * srely[eL]);
            atomicAdd(&xout[3 * r + 2], a * srelz[eL]);
        }
    }
}

// ---------------- host launch ----------------
extern "C" void kernel_launch(void* const* d_in, const int* in_sizes, int n_in,
                              void* d_out, int out_size) {
    const float* h    = (const float*)d_in[0];
    const float* x    = (const float*)d_in[1];
    const int*   ei   = (const int*)d_in[2];
    const float* embW = (const float*)d_in[3];
    const float* embb = (const float*)d_in[4];
    const float* eW1  = (const float*)d_in[5];
    const float* eb1  = (const float*)d_in[6];
    const float* eW2  = (const float*)d_in[7];
    const float* eb2  = (const float*)d_in[8];
    const float* nW1  = (const float*)d_in[9];
    const float* nb1  = (const float*)d_in[10];
    const float* nW2  = (const float*)d_in[11];
    const float* nb2  = (const float*)d_in[12];
    const float* cW1  = (const float*)d_in[13];
    const float* cb1  = (const float*)d_in[14];
    const float* cW2  = (const float*)d_in[15];
    const float* cb2  = (const float*)d_in[16];
    const int* erow = ei;
    const int* ecol = ei + EE;
    float* out = (float*)d_out;

    void* p;
    float *pU, *pV, *pZ, *pM, *pT, *pH0, *pH1, *pX0, *pX1, *pDeg;
    cudaGetSymbolAddress(&p, g_U);      pU  = (float*)p;
    cudaGetSymbolAddress(&p, g_V);      pV  = (float*)p;
    cudaGetSymbolAddress(&p, g_Zsum);   pZ  = (float*)p;
    cudaGetSymbolAddress(&p, g_M);      pM  = (float*)p;
    cudaGetSymbolAddress(&p, g_T);      pT  = (float*)p;
    cudaGetSymbolAddress(&p, g_h0);     pH0 = (float*)p;
    cudaGetSymbolAddress(&p, g_h1);     pH1 = (float*)p;
    cudaGetSymbolAddress(&p, g_x0);     pX0 = (float*)p;
    cudaGetSymbolAddress(&p, g_x1);     pX1 = (float*)p;
    cudaGetSymbolAddress(&p, g_deg);    pDeg = (float*)p;

    cudaFuncSetAttribute(edge_kernel, cudaFuncAttributeMaxDynamicSharedMemorySize,
                         EDGE_SMEM_BYTES);

    // ---- per-call precompute ----
    cudaMemsetAsync(pDeg, 0, NN * sizeof(float));
    deg_kernel<<<EE / 256, 256>>>(erow);
    precompD_kernel<<<HH, HH>>>(eW2, cW1, eb2, cb1);
    wuv_kernel<<<HH, HH>>>(eW1, eb1);
    embed_kernel<<<NN, HH>>>(h, embW, embb);
    cudaMemcpyAsync(pX0, x, NN * 3 * sizeof(float), cudaMemcpyDeviceToDevice);

    const int GB = NN / RPB;  // 625

    for (int l = 0; l < 2; l++) {
        const float* hi = (l == 0) ? pH0 : pH1;
        float*       ho = (l == 0) ? pH1 : out;
        const float* xi = (l == 0) ? pX0 : pX1;
        float*       xo = (l == 0) ? pX1 : out + (size_t)NN * HH;

        cudaMemsetAsync(pZ, 0, (size_t)NN * HH * sizeof(float));
        cudaMemcpyAsync(xo, xi, NN * 3 * sizeof(float), cudaMemcpyDeviceToDevice);

        // U|V fused: U = hi @ eW1a + eb1 ; V = hi @ eW1b
        gemm_uv<<<GB, 256>>>(hi, pU, pV);
        // fused edge pass
        edge_kernel<<<EDGE_GRID, 256, EDGE_SMEM_BYTES>>>(erow, ecol, xi, eW1 + 256 * HH,
                                                         cW2, cb2, xo);
        // M = Zsum @ eW2 + deg * eb2
        gemm128<false, false, false, true><<<GB, HH>>>(pZ, eW2, nullptr, nullptr,
                                                       eb2, pDeg, nullptr, pM);
        // T = relu(hi @ nW1a + M @ nW1b + nb1)
        gemm128<true, true, false, false><<<GB, HH>>>(hi, nW1, pM, nW1 + HH * HH,
                                                      nb1, nullptr, nullptr, pT);
        // ho = hi + T @ nW2 + nb2
        gemm128<false, false, true, false><<<GB, HH>>>(pT, nW2, nullptr, nullptr,
                                                       nb2, nullptr, hi, ho);
    }
    (void)in_sizes; (void)n_in; (void)out_size;
}